// round 8
// baseline (speedup 1.0000x reference)
#include <cuda_runtime.h>
#include <cuda_fp16.h>
#include <cstdint>

typedef unsigned int u32;
typedef long long ll;

#define Ss 4096
#define Hh 1024
#define MT (4 * Ss)

// ---------------- scratch ----------------
__device__ __align__(256) __half g_xhi[(size_t)MT * Hh];
__device__ __align__(256) __half g_xlo[(size_t)MT * Hh];
__device__ __align__(256) __half g_w[6][(size_t)Hh * Hh];
__device__ __align__(256) __half g_qkvhi[3][(size_t)MT * Hh];
__device__ __align__(256) __half g_qkvlo[3][(size_t)MT * Hh];
__device__ __align__(256) float  g_e[(size_t)4 * Ss * Ss];
__device__ __align__(256) __half g_phi[(size_t)4 * Ss * Ss];
__device__ __align__(256) __half g_plo[(size_t)4 * Ss * Ss];

// ---------------- helpers ----------------
__device__ __forceinline__ u32 s2u(const void* p) {
    u32 a;
    asm("{ .reg .u64 t; cvta.to.shared.u64 t, %1; cvt.u32.u64 %0, t; }" : "=r"(a) : "l"(p));
    return a;
}
__device__ __forceinline__ void cp16(u32 dst, const void* src) {
    asm volatile("cp.async.cg.shared.global [%0], [%1], 16;" :: "r"(dst), "l"(src) : "memory");
}
#define CP_COMMIT() asm volatile("cp.async.commit_group;" ::: "memory")
#define CP_WAIT1()  asm volatile("cp.async.wait_group 1;" ::: "memory")
#define CP_WAIT0()  asm volatile("cp.async.wait_group 0;" ::: "memory")

#define LDSM4(R, addr) \
    asm volatile("ldmatrix.sync.aligned.m8n8.x4.shared.b16 {%0,%1,%2,%3}, [%4];" \
        : "=r"((R)[0]), "=r"((R)[1]), "=r"((R)[2]), "=r"((R)[3]) : "r"(addr))
#define LDSM4T(R, addr) \
    asm volatile("ldmatrix.sync.aligned.m8n8.x4.trans.shared.b16 {%0,%1,%2,%3}, [%4];" \
        : "=r"((R)[0]), "=r"((R)[1]), "=r"((R)[2]), "=r"((R)[3]) : "r"(addr))

#define MMA_(d, a, b) \
    asm volatile("mma.sync.aligned.m16n8k16.row.col.f32.f16.f16.f32 " \
        "{%0,%1,%2,%3},{%4,%5,%6,%7},{%8,%9},{%0,%1,%2,%3};" \
        : "+f"((d)[0]), "+f"((d)[1]), "+f"((d)[2]), "+f"((d)[3]) \
        : "r"((a)[0]), "r"((a)[1]), "r"((a)[2]), "r"((a)[3]), "r"((b)[0]), "r"((b)[1]))

__device__ __forceinline__ void split1(float v, __half& h, __half& l) {
    h = __float2half_rn(v);
    l = __float2half_rn(v - __half2float(h));
}

// ---------------- SMEM layout: CTA 128x256, K-chunk 32, 3 stages ----------------
// A (NT, 128 rows x 32 halves): paired rows, addr(r,k) = (r>>1)*144 + (r&1)*64 + k*2 -> 9216 B/half
// B NT (256 rows x 32 halves): same paired layout -> 18432 B/half
// B NN (32 rows x 256 halves): pitch 264 halves (528 B) -> 16896 B/half (uses 18432 slot)
#define APB  9216
#define BPB  18432
#define STGB (2 * APB + 2 * BPB)   // 55296
#define SMEMB (3 * STGB)           // 165888

__device__ __forceinline__ u32 nt_addr(int R, int kcol) {
    return (u32)((R >> 1) * 144 + (R & 1) * 64 + kcol * 2);
}

// A load: 128 rows x 32 halves (8 KB), 2 cp16/thread
__device__ __forceinline__ void ld_a(u32 dst, const __half* g, int ld, int r0, int k0, int tid) {
#pragma unroll
    for (int i = 0; i < 2; i++) {
        int q = tid + (i << 8);
        int r = q >> 2, c = q & 3;
        cp16(dst + (u32)((r >> 1) * 144 + (r & 1) * 64 + c * 16),
             g + (size_t)(r0 + r) * ld + k0 + c * 8);
    }
}
// B NT load: 256 rows x 32 halves (16 KB), 4 cp16/thread
__device__ __forceinline__ void ld_bnt(u32 dst, const __half* g, int ld, int r0, int k0, int tid) {
#pragma unroll
    for (int i = 0; i < 4; i++) {
        int q = tid + (i << 8);
        int r = q >> 2, c = q & 3;
        cp16(dst + (u32)((r >> 1) * 144 + (r & 1) * 64 + c * 16),
             g + (size_t)(r0 + r) * ld + k0 + c * 8);
    }
}
// B NN load: 32 rows x 256 halves (16 KB), 4 cp16/thread
__device__ __forceinline__ void ld_bnn(u32 dst, const __half* g, int ld, int n0, int k0, int tid) {
#pragma unroll
    for (int i = 0; i < 4; i++) {
        int q = tid + (i << 8);
        int r = q >> 5, c = q & 31;
        cp16(dst + (u32)(r * 528 + c * 16), g + (size_t)(k0 + r) * ld + n0 + c * 8);
    }
}

// -------- HMMA GEMM: C = scale*(A @ op(B)) [+ bias], fp16x3 fp32 emulation --------
// CTA 128(M) x 256(N), warps 2(M) x 4(N), warp tile 64x64.
template <int BNN, int OUTM>
__global__ __launch_bounds__(256, 1)
void gemm_mma(const __half* __restrict__ Ah, const __half* __restrict__ Al, int lda, ll sA,
              const __half* __restrict__ Bh, const __half* __restrict__ Bl, int ldb, ll sB,
              const float* __restrict__ b0, const float* __restrict__ b1,
              const float* __restrict__ b2, float scale,
              float* __restrict__ Cf, __half* __restrict__ Chi, __half* __restrict__ Clo,
              int ldc, ll sC, int K)
{
    extern __shared__ __align__(16) char smc[];
    const u32 sb = s2u(smc);
    const int tid = threadIdx.x, wid = tid >> 5, lid = tid & 31;
    const int wm = wid >> 2, wn = wid & 3;
    const int m0 = blockIdx.y * 128, n0 = blockIdx.x * 256, z = blockIdx.z;

    const __half* pAh = Ah + (ll)z * sA;
    const __half* pAl = Al + (ll)z * sA;
    const __half* pBh = Bh + (ll)z * sB;
    const __half* pBl = Bl + (ll)z * sB;
    const float* bias = (z == 0) ? b0 : ((z == 1) ? b1 : b2);

    float acc[128];
#pragma unroll
    for (int i = 0; i < 128; i++) acc[i] = 0.0f;

    const int nc = K >> 5;

    const int aRow = wm * 64 + (lid & 15);
    const int aColS = (lid >> 4) << 3;
    int bRow, bColS;
    if (BNN) { bRow = (lid & 7) + (((lid >> 3) & 1) << 3); bColS = wn * 64 + ((lid >> 4) << 3); }
    else     { bRow = wn * 64 + (lid & 7) + ((lid >> 4) << 3); bColS = ((lid >> 3) & 1) << 3; }

    // prologue: stages 0,1 <- chunks 0,1
#pragma unroll
    for (int j = 0; j < 2; j++) {
        u32 bs = sb + (u32)j * STGB;
        int k0 = j << 5;
        ld_a(bs, pAh, lda, m0, k0, tid);
        ld_a(bs + APB, pAl, lda, m0, k0, tid);
        if (BNN) { ld_bnn(bs + 2 * APB, pBh, ldb, n0, k0, tid); ld_bnn(bs + 2 * APB + BPB, pBl, ldb, n0, k0, tid); }
        else     { ld_bnt(bs + 2 * APB, pBh, ldb, n0, k0, tid); ld_bnt(bs + 2 * APB + BPB, pBl, ldb, n0, k0, tid); }
        CP_COMMIT();
    }

    int stg = 0;
    for (int j = 0; j < nc; j++) {
        if (j + 2 < nc) CP_WAIT1(); else CP_WAIT0();
        __syncthreads();
        if (j + 2 < nc) {
            int s2 = (j + 2) % 3;
            u32 bs = sb + (u32)s2 * STGB;
            int k0 = (j + 2) << 5;
            ld_a(bs, pAh, lda, m0, k0, tid);
            ld_a(bs + APB, pAl, lda, m0, k0, tid);
            if (BNN) { ld_bnn(bs + 2 * APB, pBh, ldb, n0, k0, tid); ld_bnn(bs + 2 * APB + BPB, pBl, ldb, n0, k0, tid); }
            else     { ld_bnt(bs + 2 * APB, pBh, ldb, n0, k0, tid); ld_bnt(bs + 2 * APB + BPB, pBl, ldb, n0, k0, tid); }
            CP_COMMIT();
        }
        const u32 sS = sb + (u32)stg * STGB;
        const u32 sAh = sS, sAl = sS + APB, sBh = sS + 2 * APB, sBl = sS + 2 * APB + BPB;

#pragma unroll
        for (int kk = 0; kk < 2; kk++) {
            const int kb = kk << 4;
            u32 ah[16], al[16], bb[16];
            // A fragments hi+lo (4 m16 tiles)
#pragma unroll
            for (int mi = 0; mi < 4; mi++) {
                u32 off = nt_addr(aRow + mi * 16, kb + aColS);
                LDSM4(ah + mi * 4, sAh + off);
                LDSM4(al + mi * 4, sAl + off);
            }
            // B hi fragments (8 n8 tiles)
#pragma unroll
            for (int p4 = 0; p4 < 4; p4++) {
                if (BNN) LDSM4T(bb + p4 * 4, sBh + (u32)(((kb + bRow) * 264 + bColS + p4 * 16) * 2));
                else     LDSM4(bb + p4 * 4, sBh + nt_addr(bRow + p4 * 16, kb + bColS));
            }
            // Ah*Bh then Al*Bh (both consume bb)
#pragma unroll
            for (int mi = 0; mi < 4; mi++)
#pragma unroll
                for (int nj = 0; nj < 8; nj++) MMA_(acc + (mi * 8 + nj) * 4, ah + mi * 4, bb + nj * 2);
#pragma unroll
            for (int mi = 0; mi < 4; mi++)
#pragma unroll
                for (int nj = 0; nj < 8; nj++) MMA_(acc + (mi * 8 + nj) * 4, al + mi * 4, bb + nj * 2);
            // B lo fragments (reuse bb)
#pragma unroll
            for (int p4 = 0; p4 < 4; p4++) {
                if (BNN) LDSM4T(bb + p4 * 4, sBl + (u32)(((kb + bRow) * 264 + bColS + p4 * 16) * 2));
                else     LDSM4(bb + p4 * 4, sBl + nt_addr(bRow + p4 * 16, kb + bColS));
            }
            // Ah*Bl
#pragma unroll
            for (int mi = 0; mi < 4; mi++)
#pragma unroll
                for (int nj = 0; nj < 8; nj++) MMA_(acc + (mi * 8 + nj) * 4, ah + mi * 4, bb + nj * 2);
        }
        stg = (stg + 1) % 3;
    }

    // -------- epilogue --------
    const int g = lid >> 2, t4 = lid & 3;
#pragma unroll
    for (int mi = 0; mi < 4; mi++) {
#pragma unroll
        for (int nj = 0; nj < 8; nj++) {
            const float* c = acc + (mi * 8 + nj) * 4;
            int row = m0 + wm * 64 + mi * 16 + g;
            int col = n0 + wn * 64 + nj * 8 + t4 * 2;
            if (OUTM == 0) {
                size_t base = (size_t)((ll)z * sC) + (size_t)row * ldc + col;
                *(float2*)&Cf[base] = make_float2(c[0] * scale, c[1] * scale);
                *(float2*)&Cf[base + 8 * (size_t)ldc] = make_float2(c[2] * scale, c[3] * scale);
            } else {
                float bb0 = bias[col], bb1 = bias[col + 1];
                __half h0, h1, l0, l1;
                size_t o = (size_t)((ll)z * sC) + (size_t)row * ldc + col;
                split1(c[0] + bb0, h0, l0); split1(c[1] + bb1, h1, l1);
                *(__half2*)&Chi[o] = __halves2half2(h0, h1);
                *(__half2*)&Clo[o] = __halves2half2(l0, l1);
                split1(c[2] + bb0, h0, l0); split1(c[3] + bb1, h1, l1);
                o += 8 * (size_t)ldc;
                *(__half2*)&Chi[o] = __halves2half2(h0, h1);
                *(__half2*)&Clo[o] = __halves2half2(l0, l1);
            }
        }
    }
}

// ---------------- elementwise ----------------
__global__ void split_f(const float* __restrict__ in, __half* __restrict__ hi, __half* __restrict__ lo) {
    size_t i = (size_t)blockIdx.x * blockDim.x + threadIdx.x;
    float4 v = ((const float4*)in)[i];
    __half h0, h1, h2, h3, l0, l1, l2, l3;
    split1(v.x, h0, l0); split1(v.y, h1, l1); split1(v.z, h2, l2); split1(v.w, h3, l3);
    ((__half2*)hi)[2 * i]     = __halves2half2(h0, h1);
    ((__half2*)hi)[2 * i + 1] = __halves2half2(h2, h3);
    ((__half2*)lo)[2 * i]     = __halves2half2(l0, l1);
    ((__half2*)lo)[2 * i + 1] = __halves2half2(l2, l3);
}

__global__ void split_w3(const float* __restrict__ w0, const float* __restrict__ w1,
                         const float* __restrict__ w2, __half* __restrict__ wout) {
    const int sel = blockIdx.y;
    const float* in = (sel == 0) ? w0 : ((sel == 1) ? w1 : w2);
    __half* hi = wout + (size_t)(2 * sel) * Hh * Hh;
    __half* lo = hi + (size_t)Hh * Hh;
    size_t i = (size_t)blockIdx.x * blockDim.x + threadIdx.x;
    float4 v = ((const float4*)in)[i];
    __half h0, h1, h2, h3, l0, l1, l2, l3;
    split1(v.x, h0, l0); split1(v.y, h1, l1); split1(v.z, h2, l2); split1(v.w, h3, l3);
    ((__half2*)hi)[2 * i]     = __halves2half2(h0, h1);
    ((__half2*)hi)[2 * i + 1] = __halves2half2(h2, h3);
    ((__half2*)lo)[2 * i]     = __halves2half2(l0, l1);
    ((__half2*)lo)[2 * i + 1] = __halves2half2(l2, l3);
}

__global__ void softmax_split(const float* __restrict__ e, __half* __restrict__ phi, __half* __restrict__ plo) {
    const size_t row = blockIdx.x;
    const float4* p = (const float4*)(e + row * Ss);
    const int t = threadIdx.x;
    float4 v[4];
    float mx = -1e30f;
#pragma unroll
    for (int c = 0; c < 4; c++) {
        v[c] = p[t + c * 256];
        mx = fmaxf(mx, fmaxf(fmaxf(v[c].x, v[c].y), fmaxf(v[c].z, v[c].w)));
    }
    __shared__ float red[256];
    red[t] = mx; __syncthreads();
    for (int s = 128; s > 0; s >>= 1) { if (t < s) red[t] = fmaxf(red[t], red[t + s]); __syncthreads(); }
    mx = red[0]; __syncthreads();
    float sum = 0.0f;
#pragma unroll
    for (int c = 0; c < 4; c++) {
        v[c].x = __expf(v[c].x - mx); v[c].y = __expf(v[c].y - mx);
        v[c].z = __expf(v[c].z - mx); v[c].w = __expf(v[c].w - mx);
        sum += v[c].x + v[c].y + v[c].z + v[c].w;
    }
    red[t] = sum; __syncthreads();
    for (int s = 128; s > 0; s >>= 1) { if (t < s) red[t] += red[t + s]; __syncthreads(); }
    const float inv = 1.0f / red[0];
    __half2* ph = (__half2*)(phi + row * Ss);
    __half2* pl = (__half2*)(plo + row * Ss);
#pragma unroll
    for (int c = 0; c < 4; c++) {
        __half h0, h1, h2, h3, l0, l1, l2, l3;
        split1(v[c].x * inv, h0, l0); split1(v[c].y * inv, h1, l1);
        split1(v[c].z * inv, h2, l2); split1(v[c].w * inv, h3, l3);
        int idx = t + c * 256;
        ph[2 * idx] = __halves2half2(h0, h1); ph[2 * idx + 1] = __halves2half2(h2, h3);
        pl[2 * idx] = __halves2half2(l0, l1); pl[2 * idx + 1] = __halves2half2(l2, l3);
    }
}

// ---------------- host ----------------
extern "C" void kernel_launch(void* const* d_in, const int* in_sizes, int n_in,
                              void* d_out, int out_size)
{
    const float* x  = (const float*)d_in[0];
    const float* Wq = (const float*)d_in[1];
    const float* bq = (const float*)d_in[2];
    const float* Wk = (const float*)d_in[3];
    const float* bk = (const float*)d_in[4];
    const float* Wv = (const float*)d_in[5];
    const float* bv = (const float*)d_in[6];
    float* out = (float*)d_out;

    __half *xhi, *xlo, *w, *qkvhi, *qkvlo, *phi, *plo;
    float* e;
    cudaGetSymbolAddress((void**)&xhi, g_xhi);
    cudaGetSymbolAddress((void**)&xlo, g_xlo);
    cudaGetSymbolAddress((void**)&w,   g_w);
    cudaGetSymbolAddress((void**)&qkvhi, g_qkvhi);
    cudaGetSymbolAddress((void**)&qkvlo, g_qkvlo);
    cudaGetSymbolAddress((void**)&e,   g_e);
    cudaGetSymbolAddress((void**)&phi, g_phi);
    cudaGetSymbolAddress((void**)&plo, g_plo);

    cudaFuncSetAttribute(gemm_mma<1, 1>, cudaFuncAttributeMaxDynamicSharedMemorySize, SMEMB);
    cudaFuncSetAttribute(gemm_mma<0, 0>, cudaFuncAttributeMaxDynamicSharedMemorySize, SMEMB);
    cudaFuncSetAttribute(gemm_mma<1, 0>, cudaFuncAttributeMaxDynamicSharedMemorySize, SMEMB);

    const size_t HH = (size_t)Hh * Hh;
    const size_t QKV = (size_t)MT * Hh;

    split_f<<<(size_t)MT * Hh / 1024, 256>>>(x, xhi, xlo);
    split_w3<<<dim3(HH / 1024, 3), 256>>>(Wq, Wk, Wv, w);

    // merged projections (B NN): q,k,v = x @ W_z + b_z (fp16 hi/lo out)
    gemm_mma<1, 1><<<dim3(4, 128, 3), 256, SMEMB>>>(
        xhi, xlo, Hh, 0,
        w, w + HH, Hh, (ll)(2 * HH),
        bq, bk, bv, 1.0f,
        nullptr, qkvhi, qkvlo, Hh, (ll)QKV, Hh);

    // energy = Q @ K^T / 32 (B NT), fp32 out, per-batch
    gemm_mma<0, 0><<<dim3(16, 32, 4), 256, SMEMB>>>(
        qkvhi, qkvlo, Hh, (ll)Ss * Hh,
        qkvhi + QKV, qkvlo + QKV, Hh, (ll)Ss * Hh,
        nullptr, nullptr, nullptr, 1.0f / 32.0f,
        e, nullptr, nullptr, Ss, (ll)Ss * Ss, Hh);

    softmax_split<<<MT, 256>>>(e, phi, plo);

    // out = P @ V (B NN), fp32 out, per-batch
    gemm_mma<1, 0><<<dim3(4, 32, 4), 256, SMEMB>>>(
        phi, plo, Ss, (ll)Ss * Ss,
        qkvhi + 2 * QKV, qkvlo + 2 * QKV, Hh, (ll)Ss * Hh,
        nullptr, nullptr, nullptr, 1.0f,
        out, nullptr, nullptr, Hh, (ll)Ss * Hh, Ss);
}

// round 9
// speedup vs baseline: 1.4054x; 1.4054x over previous
#include <cuda_runtime.h>
#include <cuda_fp16.h>
#include <cstdint>

typedef unsigned int u32;
typedef long long ll;

#define Ss 4096
#define Hh 1024
#define MT (4 * Ss)

// ---------------- scratch ----------------
__device__ __align__(256) __half g_xhi[(size_t)MT * Hh];
__device__ __align__(256) __half g_xlo[(size_t)MT * Hh];
__device__ __align__(256) __half g_w[6][(size_t)Hh * Hh];
__device__ __align__(256) __half g_qkvhi[3][(size_t)MT * Hh];
__device__ __align__(256) __half g_qkvlo[3][(size_t)MT * Hh];
__device__ __align__(256) float  g_e[(size_t)4 * Ss * Ss];
__device__ __align__(256) __half g_phi[(size_t)4 * Ss * Ss];

// ---------------- helpers ----------------
__device__ __forceinline__ u32 s2u(const void* p) {
    u32 a;
    asm("{ .reg .u64 t; cvta.to.shared.u64 t, %1; cvt.u32.u64 %0, t; }" : "=r"(a) : "l"(p));
    return a;
}
__device__ __forceinline__ void cp16(u32 dst, const void* src) {
    asm volatile("cp.async.cg.shared.global [%0], [%1], 16;" :: "r"(dst), "l"(src) : "memory");
}
#define CP_COMMIT() asm volatile("cp.async.commit_group;" ::: "memory")
#define CP_WAIT1()  asm volatile("cp.async.wait_group 1;" ::: "memory")
#define CP_WAIT0()  asm volatile("cp.async.wait_group 0;" ::: "memory")

#define LDSM4(R, addr) \
    asm volatile("ldmatrix.sync.aligned.m8n8.x4.shared.b16 {%0,%1,%2,%3}, [%4];" \
        : "=r"((R)[0]), "=r"((R)[1]), "=r"((R)[2]), "=r"((R)[3]) : "r"(addr))
#define LDSM4T(R, addr) \
    asm volatile("ldmatrix.sync.aligned.m8n8.x4.trans.shared.b16 {%0,%1,%2,%3}, [%4];" \
        : "=r"((R)[0]), "=r"((R)[1]), "=r"((R)[2]), "=r"((R)[3]) : "r"(addr))

#define MMA_(d, a, b) \
    asm volatile("mma.sync.aligned.m16n8k16.row.col.f32.f16.f16.f32 " \
        "{%0,%1,%2,%3},{%4,%5,%6,%7},{%8,%9},{%0,%1,%2,%3};" \
        : "+f"((d)[0]), "+f"((d)[1]), "+f"((d)[2]), "+f"((d)[3]) \
        : "r"((a)[0]), "r"((a)[1]), "r"((a)[2]), "r"((a)[3]), "r"((b)[0]), "r"((b)[1]))

__device__ __forceinline__ void split1(float v, __half& h, __half& l) {
    h = __float2half_rn(v);
    l = __float2half_rn(v - __half2float(h));
}

// ---------------- SMEM layout: K-chunk 32, 3 stages, 2 CTAs/SM ----------------
// NT operand: logical [128][32] halves paired: addr(r,k) = (r>>1)*144 + (r&1)*64 + k*2 -> 9216 B
// NN operand: [32][128] halves, pitch 136 halves (272B) -> 8704 B (fits 9216 slot)
#define OPB  9216
#define STGB (4 * OPB)
#define SMEMB (3 * STGB)

__device__ __forceinline__ void ld_nt(u32 dst, const __half* g, int ld, int r0, int k0, int tid) {
#pragma unroll
    for (int i = 0; i < 2; i++) {
        int q = tid + (i << 8);
        int r = q >> 2, c = q & 3;
        cp16(dst + (u32)((r >> 1) * 144 + (r & 1) * 64 + c * 16),
             g + (size_t)(r0 + r) * ld + k0 + c * 8);
    }
}
__device__ __forceinline__ void ld_nn(u32 dst, const __half* g, int ld, int n0, int k0, int tid) {
#pragma unroll
    for (int i = 0; i < 2; i++) {
        int q = tid + (i << 8);
        int r = q >> 4, c = q & 15;
        cp16(dst + (u32)(r * 272 + c * 16), g + (size_t)(k0 + r) * ld + n0 + c * 8);
    }
}
__device__ __forceinline__ u32 nt_addr(int R, int kcol) {
    return (u32)((R >> 1) * 144 + (R & 1) * 64 + kcol * 2);
}

// -------- HMMA GEMM: C = scale*(A @ op(B)) [+ bias] --------
// NPROD=3: A,B both fp16 hi/lo, D = Ah*Bh + Al*Bh + Ah*Bl  (err ~2^-22)
// NPROD=2: A fp16 hi only,     D = Ah*Bh + Ah*Bl           (err ~2^-12 rms)
// BNN=0: B [N,K] (B^T). BNN=1: B [K,N]. OUTM=0: fp32*scale. OUTM=1: fp16 hi/lo + bias.
template <int BNN, int OUTM, int NPROD>
__global__ __launch_bounds__(256, 2)
void gemm_mma(const __half* __restrict__ Ah, const __half* __restrict__ Al, int lda, ll sA,
              const __half* __restrict__ Bh, const __half* __restrict__ Bl, int ldb, ll sB,
              const float* __restrict__ b0, const float* __restrict__ b1,
              const float* __restrict__ b2, float scale,
              float* __restrict__ Cf, __half* __restrict__ Chi, __half* __restrict__ Clo,
              int ldc, ll sC, int K)
{
    extern __shared__ __align__(16) char smc[];
    const u32 sb = s2u(smc);
    const int tid = threadIdx.x, wid = tid >> 5, lid = tid & 31;
    const int wm = wid >> 1, wn = wid & 1;
    const int m0 = blockIdx.y * 128, n0 = blockIdx.x * 128, z = blockIdx.z;

    const __half* pAh = Ah + (ll)z * sA;
    const __half* pAl = Al + (ll)z * sA;
    const __half* pBh = Bh + (ll)z * sB;
    const __half* pBl = Bl + (ll)z * sB;
    const float* bias = (z == 0) ? b0 : ((z == 1) ? b1 : b2);

    float acc[64];
#pragma unroll
    for (int i = 0; i < 64; i++) acc[i] = 0.0f;

    const int nc = K >> 5;

    const int aRow = wm * 32 + (lid & 15);
    const int aColS = (lid >> 4) << 3;
    int bRow, bColS;
    if (BNN) { bRow = (lid & 7) + (((lid >> 3) & 1) << 3); bColS = wn * 64 + ((lid >> 4) << 3); }
    else     { bRow = wn * 64 + (lid & 7) + ((lid >> 4) << 3); bColS = ((lid >> 3) & 1) << 3; }

    // prologue: stages 0,1 <- chunks 0,1
#pragma unroll
    for (int j = 0; j < 2; j++) {
        u32 bs = sb + (u32)j * STGB;
        int k0 = j << 5;
        ld_nt(bs, pAh, lda, m0, k0, tid);
        if (NPROD == 3) ld_nt(bs + OPB, pAl, lda, m0, k0, tid);
        if (BNN) { ld_nn(bs + 2 * OPB, pBh, ldb, n0, k0, tid); ld_nn(bs + 3 * OPB, pBl, ldb, n0, k0, tid); }
        else     { ld_nt(bs + 2 * OPB, pBh, ldb, n0, k0, tid); ld_nt(bs + 3 * OPB, pBl, ldb, n0, k0, tid); }
        CP_COMMIT();
    }

    int stg = 0;
    for (int j = 0; j < nc; j++) {
        if (j + 2 < nc) CP_WAIT1(); else CP_WAIT0();
        __syncthreads();
        if (j + 2 < nc) {
            int s2 = (j + 2) % 3;
            u32 bs = sb + (u32)s2 * STGB;
            int k0 = (j + 2) << 5;
            ld_nt(bs, pAh, lda, m0, k0, tid);
            if (NPROD == 3) ld_nt(bs + OPB, pAl, lda, m0, k0, tid);
            if (BNN) { ld_nn(bs + 2 * OPB, pBh, ldb, n0, k0, tid); ld_nn(bs + 3 * OPB, pBl, ldb, n0, k0, tid); }
            else     { ld_nt(bs + 2 * OPB, pBh, ldb, n0, k0, tid); ld_nt(bs + 3 * OPB, pBl, ldb, n0, k0, tid); }
            CP_COMMIT();
        }
        const u32 sS = sb + (u32)stg * STGB;
        const u32 sAh = sS, sAl = sS + OPB, sBh = sS + 2 * OPB, sBl = sS + 3 * OPB;

#pragma unroll
        for (int kk = 0; kk < 2; kk++) {
            const int kb = kk << 4;
            u32 ah[8], al[8], bb[16];
            // A fragments
#pragma unroll
            for (int mi = 0; mi < 2; mi++) {
                u32 off = nt_addr(aRow + mi * 16, kb + aColS);
                LDSM4(ah + mi * 4, sAh + off);
                if (NPROD == 3) LDSM4(al + mi * 4, sAl + off);
            }
            // B hi fragments
#pragma unroll
            for (int p4 = 0; p4 < 4; p4++) {
                if (BNN) LDSM4T(bb + p4 * 4, sBh + (u32)(((kb + bRow) * 136 + bColS + p4 * 16) * 2));
                else     LDSM4(bb + p4 * 4, sBh + nt_addr(bRow + p4 * 16, kb + bColS));
            }
            // Ah*Bh (and Al*Bh if 3-product)
#pragma unroll
            for (int mi = 0; mi < 2; mi++)
#pragma unroll
                for (int nj = 0; nj < 8; nj++) MMA_(acc + (mi * 8 + nj) * 4, ah + mi * 4, bb + nj * 2);
            if (NPROD == 3) {
#pragma unroll
                for (int mi = 0; mi < 2; mi++)
#pragma unroll
                    for (int nj = 0; nj < 8; nj++) MMA_(acc + (mi * 8 + nj) * 4, al + mi * 4, bb + nj * 2);
            }
            // B lo fragments (reuse bb)
#pragma unroll
            for (int p4 = 0; p4 < 4; p4++) {
                if (BNN) LDSM4T(bb + p4 * 4, sBl + (u32)(((kb + bRow) * 136 + bColS + p4 * 16) * 2));
                else     LDSM4(bb + p4 * 4, sBl + nt_addr(bRow + p4 * 16, kb + bColS));
            }
            // Ah*Bl
#pragma unroll
            for (int mi = 0; mi < 2; mi++)
#pragma unroll
                for (int nj = 0; nj < 8; nj++) MMA_(acc + (mi * 8 + nj) * 4, ah + mi * 4, bb + nj * 2);
        }
        stg = (stg + 1) % 3;
    }

    // -------- epilogue --------
    const int g = lid >> 2, t4 = lid & 3;
#pragma unroll
    for (int mi = 0; mi < 2; mi++) {
#pragma unroll
        for (int nj = 0; nj < 8; nj++) {
            const float* c = acc + (mi * 8 + nj) * 4;
            int row = m0 + wm * 32 + mi * 16 + g;
            int col = n0 + wn * 64 + nj * 8 + t4 * 2;
            if (OUTM == 0) {
                size_t base = (size_t)((ll)z * sC) + (size_t)row * ldc + col;
                *(float2*)&Cf[base] = make_float2(c[0] * scale, c[1] * scale);
                *(float2*)&Cf[base + 8 * (size_t)ldc] = make_float2(c[2] * scale, c[3] * scale);
            } else {
                float bb0 = bias[col], bb1 = bias[col + 1];
                __half h0, h1, l0, l1;
                size_t o = (size_t)((ll)z * sC) + (size_t)row * ldc + col;
                split1(c[0] + bb0, h0, l0); split1(c[1] + bb1, h1, l1);
                *(__half2*)&Chi[o] = __halves2half2(h0, h1);
                *(__half2*)&Clo[o] = __halves2half2(l0, l1);
                split1(c[2] + bb0, h0, l0); split1(c[3] + bb1, h1, l1);
                o += 8 * (size_t)ldc;
                *(__half2*)&Chi[o] = __halves2half2(h0, h1);
                *(__half2*)&Clo[o] = __halves2half2(l0, l1);
            }
        }
    }
}

// ---------------- elementwise ----------------
__global__ void split_f(const float* __restrict__ in, __half* __restrict__ hi, __half* __restrict__ lo) {
    size_t i = (size_t)blockIdx.x * blockDim.x + threadIdx.x;
    float4 v = ((const float4*)in)[i];
    __half h0, h1, h2, h3, l0, l1, l2, l3;
    split1(v.x, h0, l0); split1(v.y, h1, l1); split1(v.z, h2, l2); split1(v.w, h3, l3);
    ((__half2*)hi)[2 * i]     = __halves2half2(h0, h1);
    ((__half2*)hi)[2 * i + 1] = __halves2half2(h2, h3);
    ((__half2*)lo)[2 * i]     = __halves2half2(l0, l1);
    ((__half2*)lo)[2 * i + 1] = __halves2half2(l2, l3);
}

__global__ void split_w3(const float* __restrict__ w0, const float* __restrict__ w1,
                         const float* __restrict__ w2, __half* __restrict__ wout) {
    const int sel = blockIdx.y;
    const float* in = (sel == 0) ? w0 : ((sel == 1) ? w1 : w2);
    __half* hi = wout + (size_t)(2 * sel) * Hh * Hh;
    __half* lo = hi + (size_t)Hh * Hh;
    size_t i = (size_t)blockIdx.x * blockDim.x + threadIdx.x;
    float4 v = ((const float4*)in)[i];
    __half h0, h1, h2, h3, l0, l1, l2, l3;
    split1(v.x, h0, l0); split1(v.y, h1, l1); split1(v.z, h2, l2); split1(v.w, h3, l3);
    ((__half2*)hi)[2 * i]     = __halves2half2(h0, h1);
    ((__half2*)hi)[2 * i + 1] = __halves2half2(h2, h3);
    ((__half2*)lo)[2 * i]     = __halves2half2(l0, l1);
    ((__half2*)lo)[2 * i + 1] = __halves2half2(l2, l3);
}

// softmax -> fp16 hi only (P_lo unused by 2-product PV)
__global__ void softmax_h(const float* __restrict__ e, __half* __restrict__ phi) {
    const size_t row = blockIdx.x;
    const float4* p = (const float4*)(e + row * Ss);
    const int t = threadIdx.x;
    float4 v[4];
    float mx = -1e30f;
#pragma unroll
    for (int c = 0; c < 4; c++) {
        v[c] = p[t + c * 256];
        mx = fmaxf(mx, fmaxf(fmaxf(v[c].x, v[c].y), fmaxf(v[c].z, v[c].w)));
    }
    __shared__ float red[256];
    red[t] = mx; __syncthreads();
    for (int s = 128; s > 0; s >>= 1) { if (t < s) red[t] = fmaxf(red[t], red[t + s]); __syncthreads(); }
    mx = red[0]; __syncthreads();
    float sum = 0.0f;
#pragma unroll
    for (int c = 0; c < 4; c++) {
        v[c].x = __expf(v[c].x - mx); v[c].y = __expf(v[c].y - mx);
        v[c].z = __expf(v[c].z - mx); v[c].w = __expf(v[c].w - mx);
        sum += v[c].x + v[c].y + v[c].z + v[c].w;
    }
    red[t] = sum; __syncthreads();
    for (int s = 128; s > 0; s >>= 1) { if (t < s) red[t] += red[t + s]; __syncthreads(); }
    const float inv = 1.0f / red[0];
    __half2* ph = (__half2*)(phi + row * Ss);
#pragma unroll
    for (int c = 0; c < 4; c++) {
        __half2 a = __floats2half2_rn(v[c].x * inv, v[c].y * inv);
        __half2 b = __floats2half2_rn(v[c].z * inv, v[c].w * inv);
        int idx = t + c * 256;
        ph[2 * idx] = a; ph[2 * idx + 1] = b;
    }
}

// ---------------- host ----------------
extern "C" void kernel_launch(void* const* d_in, const int* in_sizes, int n_in,
                              void* d_out, int out_size)
{
    const float* x  = (const float*)d_in[0];
    const float* Wq = (const float*)d_in[1];
    const float* bq = (const float*)d_in[2];
    const float* Wk = (const float*)d_in[3];
    const float* bk = (const float*)d_in[4];
    const float* Wv = (const float*)d_in[5];
    const float* bv = (const float*)d_in[6];
    float* out = (float*)d_out;

    __half *xhi, *xlo, *w, *qkvhi, *qkvlo, *phi;
    float* e;
    cudaGetSymbolAddress((void**)&xhi, g_xhi);
    cudaGetSymbolAddress((void**)&xlo, g_xlo);
    cudaGetSymbolAddress((void**)&w,   g_w);
    cudaGetSymbolAddress((void**)&qkvhi, g_qkvhi);
    cudaGetSymbolAddress((void**)&qkvlo, g_qkvlo);
    cudaGetSymbolAddress((void**)&e,   g_e);
    cudaGetSymbolAddress((void**)&phi, g_phi);

    cudaFuncSetAttribute(gemm_mma<1, 1, 3>, cudaFuncAttributeMaxDynamicSharedMemorySize, SMEMB);
    cudaFuncSetAttribute(gemm_mma<0, 0, 2>, cudaFuncAttributeMaxDynamicSharedMemorySize, SMEMB);
    cudaFuncSetAttribute(gemm_mma<1, 0, 2>, cudaFuncAttributeMaxDynamicSharedMemorySize, SMEMB);

    const size_t HH = (size_t)Hh * Hh;
    const size_t QKV = (size_t)MT * Hh;

    split_f<<<(size_t)MT * Hh / 1024, 256>>>(x, xhi, xlo);
    split_w3<<<dim3(HH / 1024, 3), 256>>>(Wq, Wk, Wv, w);

    // merged projections (B NN, 3-product): q,k,v = x @ W_z + b_z (fp16 hi/lo out)
    gemm_mma<1, 1, 3><<<dim3(8, 128, 3), 256, SMEMB>>>(
        xhi, xlo, Hh, 0,
        w, w + HH, Hh, (ll)(2 * HH),
        bq, bk, bv, 1.0f,
        nullptr, qkvhi, qkvlo, Hh, (ll)QKV, Hh);

    // energy = Q @ K^T / 32 (B NT, 2-product: Q_hi only, K hi+lo), per-batch
    gemm_mma<0, 0, 2><<<dim3(32, 32, 4), 256, SMEMB>>>(
        qkvhi, qkvhi, Hh, (ll)Ss * Hh,
        qkvhi + QKV, qkvlo + QKV, Hh, (ll)Ss * Hh,
        nullptr, nullptr, nullptr, 1.0f / 32.0f,
        e, nullptr, nullptr, Ss, (ll)Ss * Ss, Hh);

    softmax_h<<<MT, 256>>>(e, phi);

    // out = P @ V (B NN, 2-product: P_hi only, V hi+lo), per-batch
    gemm_mma<1, 0, 2><<<dim3(8, 32, 4), 256, SMEMB>>>(
        phi, phi, Ss, (ll)Ss * Ss,
        qkvhi + 2 * QKV, qkvlo + 2 * QKV, Hh, (ll)Ss * Hh,
        nullptr, nullptr, nullptr, 1.0f,
        out, nullptr, nullptr, Hh, (ll)Ss * Hh, Ss);
}

// round 10
// speedup vs baseline: 1.6025x; 1.1402x over previous
#include <cuda_runtime.h>
#include <cuda_fp16.h>
#include <cstdint>

typedef unsigned int u32;
typedef long long ll;

#define Ss 4096
#define Hh 1024
#define MT (4 * Ss)

// ---------------- scratch ----------------
__device__ __align__(256) __half g_xhi[(size_t)MT * Hh];
__device__ __align__(256) __half g_w[6][(size_t)Hh * Hh];      // (Wq,Wk,Wv) x (hi,lo)
__device__ __align__(256) __half g_qkvhi[3][(size_t)MT * Hh];
__device__ __align__(256) __half g_qkvlo[3][(size_t)MT * Hh];
__device__ __align__(256) float  g_e[(size_t)4 * Ss * Ss];
__device__ __align__(256) __half g_phi[(size_t)4 * Ss * Ss];

// ---------------- helpers ----------------
__device__ __forceinline__ u32 s2u(const void* p) {
    u32 a;
    asm("{ .reg .u64 t; cvta.to.shared.u64 t, %1; cvt.u32.u64 %0, t; }" : "=r"(a) : "l"(p));
    return a;
}
__device__ __forceinline__ void cp16(u32 dst, const void* src) {
    asm volatile("cp.async.cg.shared.global [%0], [%1], 16;" :: "r"(dst), "l"(src) : "memory");
}
#define CP_COMMIT() asm volatile("cp.async.commit_group;" ::: "memory")
#define CP_WAIT2()  asm volatile("cp.async.wait_group 2;" ::: "memory")
#define CP_WAIT1()  asm volatile("cp.async.wait_group 1;" ::: "memory")
#define CP_WAIT0()  asm volatile("cp.async.wait_group 0;" ::: "memory")

#define LDSM4(R, addr) \
    asm volatile("ldmatrix.sync.aligned.m8n8.x4.shared.b16 {%0,%1,%2,%3}, [%4];" \
        : "=r"((R)[0]), "=r"((R)[1]), "=r"((R)[2]), "=r"((R)[3]) : "r"(addr))
#define LDSM4T(R, addr) \
    asm volatile("ldmatrix.sync.aligned.m8n8.x4.trans.shared.b16 {%0,%1,%2,%3}, [%4];" \
        : "=r"((R)[0]), "=r"((R)[1]), "=r"((R)[2]), "=r"((R)[3]) : "r"(addr))

#define MMA_(d, a, b) \
    asm volatile("mma.sync.aligned.m16n8k16.row.col.f32.f16.f16.f32 " \
        "{%0,%1,%2,%3},{%4,%5,%6,%7},{%8,%9},{%0,%1,%2,%3};" \
        : "+f"((d)[0]), "+f"((d)[1]), "+f"((d)[2]), "+f"((d)[3]) \
        : "r"((a)[0]), "r"((a)[1]), "r"((a)[2]), "r"((a)[3]), "r"((b)[0]), "r"((b)[1]))

__device__ __forceinline__ void split1(float v, __half& h, __half& l) {
    h = __float2half_rn(v);
    l = __float2half_rn(v - __half2float(h));
}

// ---------------- SMEM: K-chunk 32, 3 operand slots, 4 stages, 2 CTAs/SM ----------------
// NT operand: logical [128][32] halves paired: addr(r,k) = (r>>1)*144 + (r&1)*64 + k*2 -> 9216 B
// NN operand: [32][128] halves, pitch 136 halves (272B) -> 8704 B (fits 9216 slot)
#define OPB  9216
#define STGB (3 * OPB)     // A_hi | B_hi | B_lo
#define SMEMB (4 * STGB)   // 110592

__device__ __forceinline__ void ld_nt(u32 dst, const __half* g, int ld, int r0, int k0, int tid) {
#pragma unroll
    for (int i = 0; i < 2; i++) {
        int q = tid + (i << 8);
        int r = q >> 2, c = q & 3;
        cp16(dst + (u32)((r >> 1) * 144 + (r & 1) * 64 + c * 16),
             g + (size_t)(r0 + r) * ld + k0 + c * 8);
    }
}
__device__ __forceinline__ void ld_nn(u32 dst, const __half* g, int ld, int n0, int k0, int tid) {
#pragma unroll
    for (int i = 0; i < 2; i++) {
        int q = tid + (i << 8);
        int r = q >> 4, c = q & 15;
        cp16(dst + (u32)(r * 272 + c * 16), g + (size_t)(k0 + r) * ld + n0 + c * 8);
    }
}
__device__ __forceinline__ u32 nt_addr(int R, int kcol) {
    return (u32)((R >> 1) * 144 + (R & 1) * 64 + kcol * 2);
}

// -------- HMMA GEMM: C = scale*(Ah @ op(Bh+Bl)) [+ bias], 2-product fp32 emulation --------
// BNN=0: B [N,K] (B^T). BNN=1: B [K,N]. OUTM=0: fp32*scale. OUTM=1: fp16 hi/lo + bias.
template <int BNN, int OUTM>
__global__ __launch_bounds__(256, 2)
void gemm_mma(const __half* __restrict__ Ah, int lda, ll sA,
              const __half* __restrict__ Bh, const __half* __restrict__ Bl, int ldb, ll sB,
              const float* __restrict__ b0, const float* __restrict__ b1,
              const float* __restrict__ b2, float scale,
              float* __restrict__ Cf, __half* __restrict__ Chi, __half* __restrict__ Clo,
              int ldc, ll sC, int K)
{
    extern __shared__ __align__(16) char smc[];
    const u32 sb = s2u(smc);
    const int tid = threadIdx.x, wid = tid >> 5, lid = tid & 31;
    const int wm = wid >> 1, wn = wid & 1;
    const int m0 = blockIdx.y * 128, n0 = blockIdx.x * 128, z = blockIdx.z;

    const __half* pAh = Ah + (ll)z * sA;
    const __half* pBh = Bh + (ll)z * sB;
    const __half* pBl = Bl + (ll)z * sB;
    const float* bias = (z == 0) ? b0 : ((z == 1) ? b1 : b2);

    float acc[64];
#pragma unroll
    for (int i = 0; i < 64; i++) acc[i] = 0.0f;

    const int nc = K >> 5;

    const int aRow = wm * 32 + (lid & 15);
    const int aColS = (lid >> 4) << 3;
    int bRow, bColS;
    if (BNN) { bRow = (lid & 7) + (((lid >> 3) & 1) << 3); bColS = wn * 64 + ((lid >> 4) << 3); }
    else     { bRow = wn * 64 + (lid & 7) + ((lid >> 4) << 3); bColS = ((lid >> 3) & 1) << 3; }

    // prologue: stages 0..2 <- chunks 0..2
#pragma unroll
    for (int j = 0; j < 3; j++) {
        u32 bs = sb + (u32)j * STGB;
        int k0 = j << 5;
        ld_nt(bs, pAh, lda, m0, k0, tid);
        if (BNN) { ld_nn(bs + OPB, pBh, ldb, n0, k0, tid); ld_nn(bs + 2 * OPB, pBl, ldb, n0, k0, tid); }
        else     { ld_nt(bs + OPB, pBh, ldb, n0, k0, tid); ld_nt(bs + 2 * OPB, pBl, ldb, n0, k0, tid); }
        CP_COMMIT();
    }

    for (int j = 0; j < nc; j++) {
        const int rem = nc - 1 - j;
        if (rem >= 2) CP_WAIT2(); else if (rem == 1) CP_WAIT1(); else CP_WAIT0();
        __syncthreads();
        if (j + 3 < nc) {
            u32 bs = sb + (u32)((j + 3) & 3) * STGB;
            int k0 = (j + 3) << 5;
            ld_nt(bs, pAh, lda, m0, k0, tid);
            if (BNN) { ld_nn(bs + OPB, pBh, ldb, n0, k0, tid); ld_nn(bs + 2 * OPB, pBl, ldb, n0, k0, tid); }
            else     { ld_nt(bs + OPB, pBh, ldb, n0, k0, tid); ld_nt(bs + 2 * OPB, pBl, ldb, n0, k0, tid); }
            CP_COMMIT();
        }
        const u32 sS = sb + (u32)(j & 3) * STGB;
        const u32 sAh = sS, sBh = sS + OPB, sBl = sS + 2 * OPB;

#pragma unroll
        for (int kk = 0; kk < 2; kk++) {
            const int kb = kk << 4;
            u32 ah[8], bb[16];
#pragma unroll
            for (int mi = 0; mi < 2; mi++)
                LDSM4(ah + mi * 4, sAh + nt_addr(aRow + mi * 16, kb + aColS));
#pragma unroll
            for (int p4 = 0; p4 < 4; p4++) {
                if (BNN) LDSM4T(bb + p4 * 4, sBh + (u32)(((kb + bRow) * 136 + bColS + p4 * 16) * 2));
                else     LDSM4(bb + p4 * 4, sBh + nt_addr(bRow + p4 * 16, kb + bColS));
            }
#pragma unroll
            for (int mi = 0; mi < 2; mi++)
#pragma unroll
                for (int nj = 0; nj < 8; nj++) MMA_(acc + (mi * 8 + nj) * 4, ah + mi * 4, bb + nj * 2);
#pragma unroll
            for (int p4 = 0; p4 < 4; p4++) {
                if (BNN) LDSM4T(bb + p4 * 4, sBl + (u32)(((kb + bRow) * 136 + bColS + p4 * 16) * 2));
                else     LDSM4(bb + p4 * 4, sBl + nt_addr(bRow + p4 * 16, kb + bColS));
            }
#pragma unroll
            for (int mi = 0; mi < 2; mi++)
#pragma unroll
                for (int nj = 0; nj < 8; nj++) MMA_(acc + (mi * 8 + nj) * 4, ah + mi * 4, bb + nj * 2);
        }
    }

    // -------- epilogue --------
    const int g = lid >> 2, t4 = lid & 3;
#pragma unroll
    for (int mi = 0; mi < 2; mi++) {
#pragma unroll
        for (int nj = 0; nj < 8; nj++) {
            const float* c = acc + (mi * 8 + nj) * 4;
            int row = m0 + wm * 32 + mi * 16 + g;
            int col = n0 + wn * 64 + nj * 8 + t4 * 2;
            if (OUTM == 0) {
                size_t base = (size_t)((ll)z * sC) + (size_t)row * ldc + col;
                *(float2*)&Cf[base] = make_float2(c[0] * scale, c[1] * scale);
                *(float2*)&Cf[base + 8 * (size_t)ldc] = make_float2(c[2] * scale, c[3] * scale);
            } else {
                float bb0 = bias[col], bb1 = bias[col + 1];
                __half h0, h1, l0, l1;
                size_t o = (size_t)((ll)z * sC) + (size_t)row * ldc + col;
                split1(c[0] + bb0, h0, l0); split1(c[1] + bb1, h1, l1);
                *(__half2*)&Chi[o] = __halves2half2(h0, h1);
                *(__half2*)&Clo[o] = __halves2half2(l0, l1);
                split1(c[2] + bb0, h0, l0); split1(c[3] + bb1, h1, l1);
                o += 8 * (size_t)ldc;
                *(__half2*)&Chi[o] = __halves2half2(h0, h1);
                *(__half2*)&Clo[o] = __halves2half2(l0, l1);
            }
        }
    }
}

// ---------------- elementwise ----------------
// x -> fp16 hi only (x_lo unused by 2-product projections)
__global__ void conv_hi(const float* __restrict__ in, __half* __restrict__ hi) {
    size_t i = (size_t)blockIdx.x * blockDim.x + threadIdx.x;
    float4 v = ((const float4*)in)[i];
    ((__half2*)hi)[2 * i]     = __floats2half2_rn(v.x, v.y);
    ((__half2*)hi)[2 * i + 1] = __floats2half2_rn(v.z, v.w);
}

__global__ void split_w3(const float* __restrict__ w0, const float* __restrict__ w1,
                         const float* __restrict__ w2, __half* __restrict__ wout) {
    const int sel = blockIdx.y;
    const float* in = (sel == 0) ? w0 : ((sel == 1) ? w1 : w2);
    __half* hi = wout + (size_t)(2 * sel) * Hh * Hh;
    __half* lo = hi + (size_t)Hh * Hh;
    size_t i = (size_t)blockIdx.x * blockDim.x + threadIdx.x;
    float4 v = ((const float4*)in)[i];
    __half h0, h1, h2, h3, l0, l1, l2, l3;
    split1(v.x, h0, l0); split1(v.y, h1, l1); split1(v.z, h2, l2); split1(v.w, h3, l3);
    ((__half2*)hi)[2 * i]     = __halves2half2(h0, h1);
    ((__half2*)hi)[2 * i + 1] = __halves2half2(h2, h3);
    ((__half2*)lo)[2 * i]     = __halves2half2(l0, l1);
    ((__half2*)lo)[2 * i + 1] = __halves2half2(l2, l3);
}

// softmax -> fp16 hi only
__global__ void softmax_h(const float* __restrict__ e, __half* __restrict__ phi) {
    const size_t row = blockIdx.x;
    const float4* p = (const float4*)(e + row * Ss);
    const int t = threadIdx.x;
    float4 v[4];
    float mx = -1e30f;
#pragma unroll
    for (int c = 0; c < 4; c++) {
        v[c] = p[t + c * 256];
        mx = fmaxf(mx, fmaxf(fmaxf(v[c].x, v[c].y), fmaxf(v[c].z, v[c].w)));
    }
    __shared__ float red[256];
    red[t] = mx; __syncthreads();
    for (int s = 128; s > 0; s >>= 1) { if (t < s) red[t] = fmaxf(red[t], red[t + s]); __syncthreads(); }
    mx = red[0]; __syncthreads();
    float sum = 0.0f;
#pragma unroll
    for (int c = 0; c < 4; c++) {
        v[c].x = __expf(v[c].x - mx); v[c].y = __expf(v[c].y - mx);
        v[c].z = __expf(v[c].z - mx); v[c].w = __expf(v[c].w - mx);
        sum += v[c].x + v[c].y + v[c].z + v[c].w;
    }
    red[t] = sum; __syncthreads();
    for (int s = 128; s > 0; s >>= 1) { if (t < s) red[t] += red[t + s]; __syncthreads(); }
    const float inv = 1.0f / red[0];
    __half2* ph = (__half2*)(phi + row * Ss);
#pragma unroll
    for (int c = 0; c < 4; c++) {
        int idx = t + c * 256;
        ph[2 * idx]     = __floats2half2_rn(v[c].x * inv, v[c].y * inv);
        ph[2 * idx + 1] = __floats2half2_rn(v[c].z * inv, v[c].w * inv);
    }
}

// ---------------- host ----------------
extern "C" void kernel_launch(void* const* d_in, const int* in_sizes, int n_in,
                              void* d_out, int out_size)
{
    const float* x  = (const float*)d_in[0];
    const float* Wq = (const float*)d_in[1];
    const float* bq = (const float*)d_in[2];
    const float* Wk = (const float*)d_in[3];
    const float* bk = (const float*)d_in[4];
    const float* Wv = (const float*)d_in[5];
    const float* bv = (const float*)d_in[6];
    float* out = (float*)d_out;

    __half *xhi, *w, *qkvhi, *qkvlo, *phi;
    float* e;
    cudaGetSymbolAddress((void**)&xhi, g_xhi);
    cudaGetSymbolAddress((void**)&w,   g_w);
    cudaGetSymbolAddress((void**)&qkvhi, g_qkvhi);
    cudaGetSymbolAddress((void**)&qkvlo, g_qkvlo);
    cudaGetSymbolAddress((void**)&e,   g_e);
    cudaGetSymbolAddress((void**)&phi, g_phi);

    cudaFuncSetAttribute(gemm_mma<1, 1>, cudaFuncAttributeMaxDynamicSharedMemorySize, SMEMB);
    cudaFuncSetAttribute(gemm_mma<0, 0>, cudaFuncAttributeMaxDynamicSharedMemorySize, SMEMB);
    cudaFuncSetAttribute(gemm_mma<1, 0>, cudaFuncAttributeMaxDynamicSharedMemorySize, SMEMB);

    const size_t HH = (size_t)Hh * Hh;
    const size_t QKV = (size_t)MT * Hh;

    conv_hi<<<(size_t)MT * Hh / 1024, 256>>>(x, xhi);
    split_w3<<<dim3(HH / 1024, 3), 256>>>(Wq, Wk, Wv, w);

    // merged projections (B NN, 2-product: x_hi * (W_hi + W_lo)): q,k,v (fp16 hi/lo out)
    gemm_mma<1, 1><<<dim3(8, 128, 3), 256, SMEMB>>>(
        xhi, Hh, 0,
        w, w + HH, Hh, (ll)(2 * HH),
        bq, bk, bv, 1.0f,
        nullptr, qkvhi, qkvlo, Hh, (ll)QKV, Hh);

    // energy = Q @ K^T / 32 (B NT, 2-product: Q_hi * (K_hi + K_lo)), per-batch
    gemm_mma<0, 0><<<dim3(32, 32, 4), 256, SMEMB>>>(
        qkvhi, Hh, (ll)Ss * Hh,
        qkvhi + QKV, qkvlo + QKV, Hh, (ll)Ss * Hh,
        nullptr, nullptr, nullptr, 1.0f / 32.0f,
        e, nullptr, nullptr, Ss, (ll)Ss * Ss, Hh);

    softmax_h<<<MT, 256>>>(e, phi);

    // out = P @ V (B NN, 2-product: P_hi * (V_hi + V_lo)), per-batch
    gemm_mma<1, 0><<<dim3(8, 32, 4), 256, SMEMB>>>(
        phi, Ss, (ll)Ss * Ss,
        qkvhi + 2 * QKV, qkvlo + 2 * QKV, Hh, (ll)Ss * Hh,
        nullptr, nullptr, nullptr, 1.0f,
        out, nullptr, nullptr, Hh, (ll)Ss * Hh, Ss);
}

// round 11
// speedup vs baseline: 2.3012x; 1.4360x over previous
#include <cuda_runtime.h>
#include <cuda_fp16.h>
#include <cstdint>

typedef unsigned int u32;
typedef long long ll;

#define Ss 4096
#define Hh 1024
#define MT (4 * Ss)

// ---------------- scratch ----------------
__device__ __align__(256) __half g_xhi[(size_t)MT * Hh];
__device__ __align__(256) __half g_w[6][(size_t)Hh * Hh];      // (Wq,Wk,Wv) x (hi,lo)
__device__ __align__(256) __half g_qkvhi[3][(size_t)MT * Hh];  // q,k,v (fp16 hi only)
__device__ __align__(256) float  g_e[(size_t)4 * Ss * Ss];
__device__ __align__(256) __half g_phi[(size_t)4 * Ss * Ss];

// ---------------- helpers ----------------
__device__ __forceinline__ u32 s2u(const void* p) {
    u32 a;
    asm("{ .reg .u64 t; cvta.to.shared.u64 t, %1; cvt.u32.u64 %0, t; }" : "=r"(a) : "l"(p));
    return a;
}
__device__ __forceinline__ void cp16(u32 dst, const void* src) {
    asm volatile("cp.async.cg.shared.global [%0], [%1], 16;" :: "r"(dst), "l"(src) : "memory");
}
#define CP_COMMIT() asm volatile("cp.async.commit_group;" ::: "memory")
#define CP_WAIT2()  asm volatile("cp.async.wait_group 2;" ::: "memory")
#define CP_WAIT1()  asm volatile("cp.async.wait_group 1;" ::: "memory")
#define CP_WAIT0()  asm volatile("cp.async.wait_group 0;" ::: "memory")

#define LDSM4(R, addr) \
    asm volatile("ldmatrix.sync.aligned.m8n8.x4.shared.b16 {%0,%1,%2,%3}, [%4];" \
        : "=r"((R)[0]), "=r"((R)[1]), "=r"((R)[2]), "=r"((R)[3]) : "r"(addr))
#define LDSM4T(R, addr) \
    asm volatile("ldmatrix.sync.aligned.m8n8.x4.trans.shared.b16 {%0,%1,%2,%3}, [%4];" \
        : "=r"((R)[0]), "=r"((R)[1]), "=r"((R)[2]), "=r"((R)[3]) : "r"(addr))

#define MMA_(d, a, b) \
    asm volatile("mma.sync.aligned.m16n8k16.row.col.f32.f16.f16.f32 " \
        "{%0,%1,%2,%3},{%4,%5,%6,%7},{%8,%9},{%0,%1,%2,%3};" \
        : "+f"((d)[0]), "+f"((d)[1]), "+f"((d)[2]), "+f"((d)[3]) \
        : "r"((a)[0]), "r"((a)[1]), "r"((a)[2]), "r"((a)[3]), "r"((b)[0]), "r"((b)[1]))

__device__ __forceinline__ void split1(float v, __half& h, __half& l) {
    h = __float2half_rn(v);
    l = __float2half_rn(v - __half2float(h));
}

// ---------------- SMEM: K-chunk 32, (1+NPROD) slots/stage, 4 stages ----------------
// NT operand: logical [128][32] halves paired: addr(r,k) = (r>>1)*144 + (r&1)*64 + k*2 -> 9216 B
// NN operand: [32][128] halves, pitch 136 halves (272B) -> 8704 B (fits 9216 slot)
#define OPB 9216

__device__ __forceinline__ void ld_nt(u32 dst, const __half* g, int ld, int r0, int k0, int tid) {
#pragma unroll
    for (int i = 0; i < 2; i++) {
        int q = tid + (i << 8);
        int r = q >> 2, c = q & 3;
        cp16(dst + (u32)((r >> 1) * 144 + (r & 1) * 64 + c * 16),
             g + (size_t)(r0 + r) * ld + k0 + c * 8);
    }
}
__device__ __forceinline__ void ld_nn(u32 dst, const __half* g, int ld, int n0, int k0, int tid) {
#pragma unroll
    for (int i = 0; i < 2; i++) {
        int q = tid + (i << 8);
        int r = q >> 4, c = q & 15;
        cp16(dst + (u32)(r * 272 + c * 16), g + (size_t)(k0 + r) * ld + n0 + c * 8);
    }
}
__device__ __forceinline__ u32 nt_addr(int R, int kcol) {
    return (u32)((R >> 1) * 144 + (R & 1) * 64 + kcol * 2);
}

// -------- HMMA GEMM: C = scale*(Ah @ op(B)) [+ bias] --------
// NPROD=2: B = Bh + Bl (2 MMA products). NPROD=1: B = Bh only (pure fp16 operands).
// BNN=0: B [N,K] (B^T). BNN=1: B [K,N]. OUTM=0: fp32*scale. OUTM=1: fp16 hi + bias.
template <int BNN, int OUTM, int NPROD>
__global__ __launch_bounds__(256, 2)
void gemm_mma(const __half* __restrict__ Ah, int lda, ll sA,
              const __half* __restrict__ Bh, const __half* __restrict__ Bl, int ldb, ll sB,
              const float* __restrict__ b0, const float* __restrict__ b1,
              const float* __restrict__ b2, float scale,
              float* __restrict__ Cf, __half* __restrict__ Chi,
              int ldc, ll sC, int K)
{
    const u32 STGB = (u32)((1 + NPROD) * OPB);
    extern __shared__ __align__(16) char smc[];
    const u32 sb = s2u(smc);
    const int tid = threadIdx.x, wid = tid >> 5, lid = tid & 31;
    const int wm = wid >> 1, wn = wid & 1;
    const int m0 = blockIdx.y * 128, n0 = blockIdx.x * 128, z = blockIdx.z;

    const __half* pAh = Ah + (ll)z * sA;
    const __half* pBh = Bh + (ll)z * sB;
    const __half* pBl = Bl + (ll)z * sB;
    const float* bias = (z == 0) ? b0 : ((z == 1) ? b1 : b2);

    float acc[64];
#pragma unroll
    for (int i = 0; i < 64; i++) acc[i] = 0.0f;

    const int nc = K >> 5;

    const int aRow = wm * 32 + (lid & 15);
    const int aColS = (lid >> 4) << 3;
    int bRow, bColS;
    if (BNN) { bRow = (lid & 7) + (((lid >> 3) & 1) << 3); bColS = wn * 64 + ((lid >> 4) << 3); }
    else     { bRow = wn * 64 + (lid & 7) + ((lid >> 4) << 3); bColS = ((lid >> 3) & 1) << 3; }

    // prologue: stages 0..2 <- chunks 0..2
#pragma unroll
    for (int j = 0; j < 3; j++) {
        u32 bs = sb + (u32)j * STGB;
        int k0 = j << 5;
        ld_nt(bs, pAh, lda, m0, k0, tid);
        if (BNN) {
            ld_nn(bs + OPB, pBh, ldb, n0, k0, tid);
            if (NPROD == 2) ld_nn(bs + 2 * OPB, pBl, ldb, n0, k0, tid);
        } else {
            ld_nt(bs + OPB, pBh, ldb, n0, k0, tid);
            if (NPROD == 2) ld_nt(bs + 2 * OPB, pBl, ldb, n0, k0, tid);
        }
        CP_COMMIT();
    }

    for (int j = 0; j < nc; j++) {
        const int rem = nc - 1 - j;
        if (rem >= 2) CP_WAIT2(); else if (rem == 1) CP_WAIT1(); else CP_WAIT0();
        __syncthreads();
        if (j + 3 < nc) {
            u32 bs = sb + (u32)((j + 3) & 3) * STGB;
            int k0 = (j + 3) << 5;
            ld_nt(bs, pAh, lda, m0, k0, tid);
            if (BNN) {
                ld_nn(bs + OPB, pBh, ldb, n0, k0, tid);
                if (NPROD == 2) ld_nn(bs + 2 * OPB, pBl, ldb, n0, k0, tid);
            } else {
                ld_nt(bs + OPB, pBh, ldb, n0, k0, tid);
                if (NPROD == 2) ld_nt(bs + 2 * OPB, pBl, ldb, n0, k0, tid);
            }
            CP_COMMIT();
        }
        const u32 sS = sb + (u32)(j & 3) * STGB;
        const u32 sAh = sS, sBh = sS + OPB, sBl = sS + 2 * OPB;

#pragma unroll
        for (int kk = 0; kk < 2; kk++) {
            const int kb = kk << 4;
            u32 ah[8], bb[16];
#pragma unroll
            for (int mi = 0; mi < 2; mi++)
                LDSM4(ah + mi * 4, sAh + nt_addr(aRow + mi * 16, kb + aColS));
#pragma unroll
            for (int p4 = 0; p4 < 4; p4++) {
                if (BNN) LDSM4T(bb + p4 * 4, sBh + (u32)(((kb + bRow) * 136 + bColS + p4 * 16) * 2));
                else     LDSM4(bb + p4 * 4, sBh + nt_addr(bRow + p4 * 16, kb + bColS));
            }
#pragma unroll
            for (int mi = 0; mi < 2; mi++)
#pragma unroll
                for (int nj = 0; nj < 8; nj++) MMA_(acc + (mi * 8 + nj) * 4, ah + mi * 4, bb + nj * 2);
            if (NPROD == 2) {
#pragma unroll
                for (int p4 = 0; p4 < 4; p4++) {
                    if (BNN) LDSM4T(bb + p4 * 4, sBl + (u32)(((kb + bRow) * 136 + bColS + p4 * 16) * 2));
                    else     LDSM4(bb + p4 * 4, sBl + nt_addr(bRow + p4 * 16, kb + bColS));
                }
#pragma unroll
                for (int mi = 0; mi < 2; mi++)
#pragma unroll
                    for (int nj = 0; nj < 8; nj++) MMA_(acc + (mi * 8 + nj) * 4, ah + mi * 4, bb + nj * 2);
            }
        }
    }

    // -------- epilogue --------
    const int g = lid >> 2, t4 = lid & 3;
#pragma unroll
    for (int mi = 0; mi < 2; mi++) {
#pragma unroll
        for (int nj = 0; nj < 8; nj++) {
            const float* c = acc + (mi * 8 + nj) * 4;
            int row = m0 + wm * 32 + mi * 16 + g;
            int col = n0 + wn * 64 + nj * 8 + t4 * 2;
            if (OUTM == 0) {
                size_t base = (size_t)((ll)z * sC) + (size_t)row * ldc + col;
                *(float2*)&Cf[base] = make_float2(c[0] * scale, c[1] * scale);
                *(float2*)&Cf[base + 8 * (size_t)ldc] = make_float2(c[2] * scale, c[3] * scale);
            } else {
                float bb0 = bias[col], bb1 = bias[col + 1];
                size_t o = (size_t)((ll)z * sC) + (size_t)row * ldc + col;
                *(__half2*)&Chi[o] = __floats2half2_rn(c[0] + bb0, c[1] + bb1);
                o += 8 * (size_t)ldc;
                *(__half2*)&Chi[o] = __floats2half2_rn(c[2] + bb0, c[3] + bb1);
            }
        }
    }
}

// ---------------- elementwise ----------------
__global__ void conv_hi(const float* __restrict__ in, __half* __restrict__ hi) {
    size_t i = (size_t)blockIdx.x * blockDim.x + threadIdx.x;
    float4 v = ((const float4*)in)[i];
    ((__half2*)hi)[2 * i]     = __floats2half2_rn(v.x, v.y);
    ((__half2*)hi)[2 * i + 1] = __floats2half2_rn(v.z, v.w);
}

__global__ void split_w3(const float* __restrict__ w0, const float* __restrict__ w1,
                         const float* __restrict__ w2, __half* __restrict__ wout) {
    const int sel = blockIdx.y;
    const float* in = (sel == 0) ? w0 : ((sel == 1) ? w1 : w2);
    __half* hi = wout + (size_t)(2 * sel) * Hh * Hh;
    __half* lo = hi + (size_t)Hh * Hh;
    size_t i = (size_t)blockIdx.x * blockDim.x + threadIdx.x;
    float4 v = ((const float4*)in)[i];
    __half h0, h1, h2, h3, l0, l1, l2, l3;
    split1(v.x, h0, l0); split1(v.y, h1, l1); split1(v.z, h2, l2); split1(v.w, h3, l3);
    ((__half2*)hi)[2 * i]     = __halves2half2(h0, h1);
    ((__half2*)hi)[2 * i + 1] = __halves2half2(h2, h3);
    ((__half2*)lo)[2 * i]     = __halves2half2(l0, l1);
    ((__half2*)lo)[2 * i + 1] = __halves2half2(l2, l3);
}

__global__ void softmax_h(const float* __restrict__ e, __half* __restrict__ phi) {
    const size_t row = blockIdx.x;
    const float4* p = (const float4*)(e + row * Ss);
    const int t = threadIdx.x;
    float4 v[4];
    float mx = -1e30f;
#pragma unroll
    for (int c = 0; c < 4; c++) {
        v[c] = p[t + c * 256];
        mx = fmaxf(mx, fmaxf(fmaxf(v[c].x, v[c].y), fmaxf(v[c].z, v[c].w)));
    }
    __shared__ float red[256];
    red[t] = mx; __syncthreads();
    for (int s = 128; s > 0; s >>= 1) { if (t < s) red[t] = fmaxf(red[t], red[t + s]); __syncthreads(); }
    mx = red[0]; __syncthreads();
    float sum = 0.0f;
#pragma unroll
    for (int c = 0; c < 4; c++) {
        v[c].x = __expf(v[c].x - mx); v[c].y = __expf(v[c].y - mx);
        v[c].z = __expf(v[c].z - mx); v[c].w = __expf(v[c].w - mx);
        sum += v[c].x + v[c].y + v[c].z + v[c].w;
    }
    red[t] = sum; __syncthreads();
    for (int s = 128; s > 0; s >>= 1) { if (t < s) red[t] += red[t + s]; __syncthreads(); }
    const float inv = 1.0f / red[0];
    __half2* ph = (__half2*)(phi + row * Ss);
#pragma unroll
    for (int c = 0; c < 4; c++) {
        int idx = t + c * 256;
        ph[2 * idx]     = __floats2half2_rn(v[c].x * inv, v[c].y * inv);
        ph[2 * idx + 1] = __floats2half2_rn(v[c].z * inv, v[c].w * inv);
    }
}

// ---------------- host ----------------
extern "C" void kernel_launch(void* const* d_in, const int* in_sizes, int n_in,
                              void* d_out, int out_size)
{
    const float* x  = (const float*)d_in[0];
    const float* Wq = (const float*)d_in[1];
    const float* bq = (const float*)d_in[2];
    const float* Wk = (const float*)d_in[3];
    const float* bk = (const float*)d_in[4];
    const float* Wv = (const float*)d_in[5];
    const float* bv = (const float*)d_in[6];
    float* out = (float*)d_out;

    __half *xhi, *w, *qkvhi, *phi;
    float* e;
    cudaGetSymbolAddress((void**)&xhi, g_xhi);
    cudaGetSymbolAddress((void**)&w,   g_w);
    cudaGetSymbolAddress((void**)&qkvhi, g_qkvhi);
    cudaGetSymbolAddress((void**)&e,   g_e);
    cudaGetSymbolAddress((void**)&phi, g_phi);

    const int SM_P2 = 4 * 3 * OPB;   // 110592 (projections, NPROD=2)
    const int SM_P1 = 4 * 2 * OPB;   // 73728  (QK/PV, NPROD=1)
    cudaFuncSetAttribute(gemm_mma<1, 1, 2>, cudaFuncAttributeMaxDynamicSharedMemorySize, SM_P2);
    cudaFuncSetAttribute(gemm_mma<0, 0, 1>, cudaFuncAttributeMaxDynamicSharedMemorySize, SM_P1);
    cudaFuncSetAttribute(gemm_mma<1, 0, 1>, cudaFuncAttributeMaxDynamicSharedMemorySize, SM_P1);

    const size_t HH = (size_t)Hh * Hh;
    const size_t QKV = (size_t)MT * Hh;

    conv_hi<<<(size_t)MT * Hh / 1024, 256>>>(x, xhi);
    split_w3<<<dim3(HH / 1024, 3), 256>>>(Wq, Wk, Wv, w);

    // merged projections (B NN, 2-product: x_hi * (W_hi + W_lo)), fp16 hi out + bias
    gemm_mma<1, 1, 2><<<dim3(8, 128, 3), 256, SM_P2>>>(
        xhi, Hh, 0,
        w, w + HH, Hh, (ll)(2 * HH),
        bq, bk, bv, 1.0f,
        nullptr, qkvhi, Hh, (ll)QKV, Hh);

    // energy = Q_h @ K_h^T / 32 (B NT, single product), fp32 out, per-batch
    gemm_mma<0, 0, 1><<<dim3(32, 32, 4), 256, SM_P1>>>(
        qkvhi, Hh, (ll)Ss * Hh,
        qkvhi + QKV, nullptr, Hh, (ll)Ss * Hh,
        nullptr, nullptr, nullptr, 1.0f / 32.0f,
        e, nullptr, Ss, (ll)Ss * Ss, Hh);

    softmax_h<<<MT, 256>>>(e, phi);

    // out = P_h @ V_h (B NN, single product), fp32 out, per-batch
    gemm_mma<1, 0, 1><<<dim3(8, 32, 4), 256, SM_P1>>>(
        phi, Ss, (ll)Ss * Ss,
        qkvhi + 2 * QKV, nullptr, Hh, (ll)Ss * Hh,
        nullptr, nullptr, nullptr, 1.0f,
        out, nullptr, Hh, (ll)Ss * Hh, Ss);
}

// round 12
// speedup vs baseline: 2.8361x; 1.2324x over previous
#include <cuda_runtime.h>
#include <cuda_fp16.h>
#include <cstdint>

typedef unsigned int u32;
typedef long long ll;

#define Ss 4096
#define Hh 1024
#define MT (4 * Ss)

// ---------------- scratch ----------------
__device__ __align__(256) __half g_xhi[(size_t)MT * Hh];
__device__ __align__(256) __half g_wh[3][(size_t)Hh * Hh];     // Wq,Wk,Wv fp16
__device__ __align__(256) __half g_qkvhi[3][(size_t)MT * Hh];  // q,k,v fp16
__device__ __align__(256) float  g_e[(size_t)4 * Ss * Ss];
__device__ __align__(256) __half g_phi[(size_t)4 * Ss * Ss];

// ---------------- helpers ----------------
__device__ __forceinline__ u32 s2u(const void* p) {
    u32 a;
    asm("{ .reg .u64 t; cvta.to.shared.u64 t, %1; cvt.u32.u64 %0, t; }" : "=r"(a) : "l"(p));
    return a;
}
__device__ __forceinline__ void cp16(u32 dst, const void* src) {
    asm volatile("cp.async.cg.shared.global [%0], [%1], 16;" :: "r"(dst), "l"(src) : "memory");
}
#define CP_COMMIT() asm volatile("cp.async.commit_group;" ::: "memory")
#define CP_WAIT1()  asm volatile("cp.async.wait_group 1;" ::: "memory")
#define CP_WAIT0()  asm volatile("cp.async.wait_group 0;" ::: "memory")

#define LDSM4(R, addr) \
    asm volatile("ldmatrix.sync.aligned.m8n8.x4.shared.b16 {%0,%1,%2,%3}, [%4];" \
        : "=r"((R)[0]), "=r"((R)[1]), "=r"((R)[2]), "=r"((R)[3]) : "r"(addr))
#define LDSM4T(R, addr) \
    asm volatile("ldmatrix.sync.aligned.m8n8.x4.trans.shared.b16 {%0,%1,%2,%3}, [%4];" \
        : "=r"((R)[0]), "=r"((R)[1]), "=r"((R)[2]), "=r"((R)[3]) : "r"(addr))

#define MMA_(d, a, b) \
    asm volatile("mma.sync.aligned.m16n8k16.row.col.f32.f16.f16.f32 " \
        "{%0,%1,%2,%3},{%4,%5,%6,%7},{%8,%9},{%0,%1,%2,%3};" \
        : "+f"((d)[0]), "+f"((d)[1]), "+f"((d)[2]), "+f"((d)[3]) \
        : "r"((a)[0]), "r"((a)[1]), "r"((a)[2]), "r"((a)[3]), "r"((b)[0]), "r"((b)[1]))

// ---------------- SMEM: K-chunk 64, 2 operand slots/stage, 3 stages, 2 CTAs/SM ----------------
// NT operand: 128 rows x 64 halves, pitch 72 halves (144B) -> 18432 B; lanes 0-7 fill one
//   128B row during cp.async -> conflict-free writes; ldmatrix rows at 144B stride.
// NN operand: 64 rows x 128 halves, pitch 136 halves (272B) -> 17408 B (fits 18432 slot).
#define OPB  18432
#define STGB (2 * OPB)     // 36864
#define SMEMB (3 * STGB)   // 110592

__device__ __forceinline__ void ld_nt(u32 dst, const __half* g, int ld, int r0, int k0, int tid) {
#pragma unroll
    for (int i = 0; i < 4; i++) {
        int q = tid + (i << 8);
        int r = q >> 3, c = q & 7;
        cp16(dst + (u32)(r * 144 + c * 16), g + (size_t)(r0 + r) * ld + k0 + c * 8);
    }
}
__device__ __forceinline__ void ld_nn(u32 dst, const __half* g, int ld, int n0, int k0, int tid) {
#pragma unroll
    for (int i = 0; i < 4; i++) {
        int q = tid + (i << 8);
        int r = q >> 4, c = q & 15;
        cp16(dst + (u32)(r * 272 + c * 16), g + (size_t)(k0 + r) * ld + n0 + c * 8);
    }
}

// -------- HMMA GEMM: C = scale*(Ah @ op(Bh)) [+ bias], pure fp16 operands, fp32 accum --------
// BNN=0: B [N,K] (B^T). BNN=1: B [K,N]. OUTM=0: fp32*scale. OUTM=1: fp16 + bias.
template <int BNN, int OUTM>
__global__ __launch_bounds__(256, 2)
void gemm_mma(const __half* __restrict__ Ah, int lda, ll sA,
              const __half* __restrict__ Bh, int ldb, ll sB,
              const float* __restrict__ b0, const float* __restrict__ b1,
              const float* __restrict__ b2, float scale,
              float* __restrict__ Cf, __half* __restrict__ Chi,
              int ldc, ll sC, int K)
{
    extern __shared__ __align__(16) char smc[];
    const u32 sb = s2u(smc);
    const int tid = threadIdx.x, wid = tid >> 5, lid = tid & 31;
    const int wm = wid >> 1, wn = wid & 1;
    const int m0 = blockIdx.y * 128, n0 = blockIdx.x * 128, z = blockIdx.z;

    const __half* pAh = Ah + (ll)z * sA;
    const __half* pBh = Bh + (ll)z * sB;
    const float* bias = (z == 0) ? b0 : ((z == 1) ? b1 : b2);

    float acc[64];
#pragma unroll
    for (int i = 0; i < 64; i++) acc[i] = 0.0f;

    const int nc = K >> 6;

    const int aRow = wm * 32 + (lid & 15);
    const int aColS = (lid >> 4) << 3;
    int bRow, bColS;
    if (BNN) { bRow = (lid & 7) + (((lid >> 3) & 1) << 3); bColS = wn * 64 + ((lid >> 4) << 3); }
    else     { bRow = wn * 64 + (lid & 7) + ((lid >> 4) << 3); bColS = ((lid >> 3) & 1) << 3; }

    // prologue: stages 0,1 <- chunks 0,1
#pragma unroll
    for (int j = 0; j < 2; j++) {
        u32 bs = sb + (u32)j * STGB;
        int k0 = j << 6;
        ld_nt(bs, pAh, lda, m0, k0, tid);
        if (BNN) ld_nn(bs + OPB, pBh, ldb, n0, k0, tid);
        else     ld_nt(bs + OPB, pBh, ldb, n0, k0, tid);
        CP_COMMIT();
    }

    int stg = 0;
    for (int j = 0; j < nc; j++) {
        if (j + 2 < nc) CP_WAIT1(); else CP_WAIT0();
        __syncthreads();
        if (j + 2 < nc) {
            int s2 = (j + 2) % 3;
            u32 bs = sb + (u32)s2 * STGB;
            int k0 = (j + 2) << 6;
            ld_nt(bs, pAh, lda, m0, k0, tid);
            if (BNN) ld_nn(bs + OPB, pBh, ldb, n0, k0, tid);
            else     ld_nt(bs + OPB, pBh, ldb, n0, k0, tid);
            CP_COMMIT();
        }
        const u32 sS = sb + (u32)stg * STGB;
        const u32 sAh = sS, sBh = sS + OPB;

#pragma unroll
        for (int kk = 0; kk < 4; kk++) {
            const int kb = kk << 4;
            u32 ah[8], bb[16];
#pragma unroll
            for (int mi = 0; mi < 2; mi++)
                LDSM4(ah + mi * 4, sAh + (u32)(((aRow + mi * 16) * 72 + kb + aColS) * 2));
#pragma unroll
            for (int p4 = 0; p4 < 4; p4++) {
                if (BNN) LDSM4T(bb + p4 * 4, sBh + (u32)(((kb + bRow) * 136 + bColS + p4 * 16) * 2));
                else     LDSM4(bb + p4 * 4, sBh + (u32)(((bRow + p4 * 16) * 72 + kb + bColS) * 2));
            }
#pragma unroll
            for (int mi = 0; mi < 2; mi++)
#pragma unroll
                for (int nj = 0; nj < 8; nj++) MMA_(acc + (mi * 8 + nj) * 4, ah + mi * 4, bb + nj * 2);
        }
        stg = (stg + 1) % 3;
    }

    // -------- epilogue --------
    const int g = lid >> 2, t4 = lid & 3;
#pragma unroll
    for (int mi = 0; mi < 2; mi++) {
#pragma unroll
        for (int nj = 0; nj < 8; nj++) {
            const float* c = acc + (mi * 8 + nj) * 4;
            int row = m0 + wm * 32 + mi * 16 + g;
            int col = n0 + wn * 64 + nj * 8 + t4 * 2;
            if (OUTM == 0) {
                size_t base = (size_t)((ll)z * sC) + (size_t)row * ldc + col;
                *(float2*)&Cf[base] = make_float2(c[0] * scale, c[1] * scale);
                *(float2*)&Cf[base + 8 * (size_t)ldc] = make_float2(c[2] * scale, c[3] * scale);
            } else {
                float bb0 = bias[col], bb1 = bias[col + 1];
                size_t o = (size_t)((ll)z * sC) + (size_t)row * ldc + col;
                *(__half2*)&Chi[o] = __floats2half2_rn(c[0] + bb0, c[1] + bb1);
                o += 8 * (size_t)ldc;
                *(__half2*)&Chi[o] = __floats2half2_rn(c[2] + bb0, c[3] + bb1);
            }
        }
    }
}

// ---------------- elementwise ----------------
__global__ void conv_hi(const float* __restrict__ in, __half* __restrict__ hi) {
    size_t i = (size_t)blockIdx.x * blockDim.x + threadIdx.x;
    float4 v = ((const float4*)in)[i];
    ((__half2*)hi)[2 * i]     = __floats2half2_rn(v.x, v.y);
    ((__half2*)hi)[2 * i + 1] = __floats2half2_rn(v.z, v.w);
}

__global__ void conv_w3(const float* __restrict__ w0, const float* __restrict__ w1,
                        const float* __restrict__ w2, __half* __restrict__ wout) {
    const int sel = blockIdx.y;
    const float* in = (sel == 0) ? w0 : ((sel == 1) ? w1 : w2);
    __half* hi = wout + (size_t)sel * Hh * Hh;
    size_t i = (size_t)blockIdx.x * blockDim.x + threadIdx.x;
    float4 v = ((const float4*)in)[i];
    ((__half2*)hi)[2 * i]     = __floats2half2_rn(v.x, v.y);
    ((__half2*)hi)[2 * i + 1] = __floats2half2_rn(v.z, v.w);
}

__global__ void softmax_h(const float* __restrict__ e, __half* __restrict__ phi) {
    const size_t row = blockIdx.x;
    const float4* p = (const float4*)(e + row * Ss);
    const int t = threadIdx.x;
    float4 v[4];
    float mx = -1e30f;
#pragma unroll
    for (int c = 0; c < 4; c++) {
        v[c] = p[t + c * 256];
        mx = fmaxf(mx, fmaxf(fmaxf(v[c].x, v[c].y), fmaxf(v[c].z, v[c].w)));
    }
    __shared__ float red[256];
    red[t] = mx; __syncthreads();
    for (int s = 128; s > 0; s >>= 1) { if (t < s) red[t] = fmaxf(red[t], red[t + s]); __syncthreads(); }
    mx = red[0]; __syncthreads();
    float sum = 0.0f;
#pragma unroll
    for (int c = 0; c < 4; c++) {
        v[c].x = __expf(v[c].x - mx); v[c].y = __expf(v[c].y - mx);
        v[c].z = __expf(v[c].z - mx); v[c].w = __expf(v[c].w - mx);
        sum += v[c].x + v[c].y + v[c].z + v[c].w;
    }
    red[t] = sum; __syncthreads();
    for (int s = 128; s > 0; s >>= 1) { if (t < s) red[t] += red[t + s]; __syncthreads(); }
    const float inv = 1.0f / red[0];
    __half2* ph = (__half2*)(phi + row * Ss);
#pragma unroll
    for (int c = 0; c < 4; c++) {
        int idx = t + c * 256;
        ph[2 * idx]     = __floats2half2_rn(v[c].x * inv, v[c].y * inv);
        ph[2 * idx + 1] = __floats2half2_rn(v[c].z * inv, v[c].w * inv);
    }
}

// ---------------- host ----------------
extern "C" void kernel_launch(void* const* d_in, const int* in_sizes, int n_in,
                              void* d_out, int out_size)
{
    const float* x  = (const float*)d_in[0];
    const float* Wq = (const float*)d_in[1];
    const float* bq = (const float*)d_in[2];
    const float* Wk = (const float*)d_in[3];
    const float* bk = (const float*)d_in[4];
    const float* Wv = (const float*)d_in[5];
    const float* bv = (const float*)d_in[6];
    float* out = (float*)d_out;

    __half *xhi, *wh, *qkvhi, *phi;
    float* e;
    cudaGetSymbolAddress((void**)&xhi, g_xhi);
    cudaGetSymbolAddress((void**)&wh,  g_wh);
    cudaGetSymbolAddress((void**)&qkvhi, g_qkvhi);
    cudaGetSymbolAddress((void**)&e,   g_e);
    cudaGetSymbolAddress((void**)&phi, g_phi);

    cudaFuncSetAttribute(gemm_mma<1, 1>, cudaFuncAttributeMaxDynamicSharedMemorySize, SMEMB);
    cudaFuncSetAttribute(gemm_mma<0, 0>, cudaFuncAttributeMaxDynamicSharedMemorySize, SMEMB);
    cudaFuncSetAttribute(gemm_mma<1, 0>, cudaFuncAttributeMaxDynamicSharedMemorySize, SMEMB);

    const size_t HH = (size_t)Hh * Hh;
    const size_t QKV = (size_t)MT * Hh;

    conv_hi<<<(size_t)MT * Hh / 1024, 256>>>(x, xhi);
    conv_w3<<<dim3(HH / 1024, 3), 256>>>(Wq, Wk, Wv, wh);

    // merged projections (B NN): q,k,v = x_h @ W_h + b (fp16 out)
    gemm_mma<1, 1><<<dim3(8, 128, 3), 256, SMEMB>>>(
        xhi, Hh, 0,
        wh, Hh, (ll)HH,
        bq, bk, bv, 1.0f,
        nullptr, qkvhi, Hh, (ll)QKV, Hh);

    // energy = Q_h @ K_h^T / 32 (B NT), fp32 out, per-batch
    gemm_mma<0, 0><<<dim3(32, 32, 4), 256, SMEMB>>>(
        qkvhi, Hh, (ll)Ss * Hh,
        qkvhi + QKV, Hh, (ll)Ss * Hh,
        nullptr, nullptr, nullptr, 1.0f / 32.0f,
        e, nullptr, Ss, (ll)Ss * Ss, Hh);

    softmax_h<<<MT, 256>>>(e, phi);

    // out = P_h @ V_h (B NN), fp32 out, per-batch
    gemm_mma<1, 0><<<dim3(8, 32, 4), 256, SMEMB>>>(
        phi, Ss, (ll)Ss * Ss,
        qkvhi + 2 * QKV, Hh, (ll)Ss * Hh,
        nullptr, nullptr, nullptr, 1.0f,
        out, nullptr, Hh, (ll)Ss * Hh, Ss);
}